// round 4
// baseline (speedup 1.0000x reference)
#include <cuda_runtime.h>

#define NB 16
#define NP 2048
#define NC 512
#define BP (NB * NP)
#define ITI 128
#define JCH 1024

// ---------------- device scratch (no allocations allowed) ----------------
__device__ unsigned long long g_best[NB * 3 * NP]; // packed (iou_bits<<11)|(2047-j), 0 = none
__device__ unsigned char g_seed[NB * NP];          // per-proposal seed bits (label-gated)
__device__ int g_imb[4];
__device__ float g_loss;
__device__ unsigned char g_a[BP];
__device__ float g_w[BP];

// ---------------- K_seeds: seed masks + fallback + global init ----------------
__global__ void __launch_bounds__(256) k_seeds(const float4* __restrict__ ps,
                                               const float* __restrict__ labels) {
    int b = blockIdx.x;
    int t = threadIdx.x;

    // zero accumulators (spread over the 16*256 threads of this launch)
    {
        int gid = b * 256 + t;
        for (int idx = gid; idx < NB * 3 * NP; idx += NB * 256) g_best[idx] = 0ull;
        if (gid < 4) g_imb[gid] = 0;
        if (gid == 4) g_loss = 0.0f;
    }

    __shared__ float smax[3][256];
    __shared__ int   sidx[3][256];
    __shared__ int   scnt[3][256];
    __shared__ int   fres[3];
    __shared__ int   fcnt[3];

    float mx[3] = {-1e30f, -1e30f, -1e30f};
    int   mi[3] = {0, 0, 0};
    int   cn[3] = {0, 0, 0};
    unsigned char bits[NP / 256];

#pragma unroll
    for (int m = 0; m < NP / 256; ++m) {
        int j = t + m * 256;                 // ascending within thread -> first-occurrence ties
        float4 s = ps[b * NP + j];
        float sc[3] = {s.x, s.y, s.z};
        unsigned bb = 0;
#pragma unroll
        for (int c = 0; c < 3; ++c) {
            if (sc[c] > 0.5f) { bb |= (1u << c); cn[c]++; }
            if (sc[c] > mx[c]) { mx[c] = sc[c]; mi[c] = j; }
        }
        bits[m] = (unsigned char)bb;
    }
#pragma unroll
    for (int c = 0; c < 3; ++c) { smax[c][t] = mx[c]; sidx[c][t] = mi[c]; scnt[c][t] = cn[c]; }
    __syncthreads();

    if (t < 3) {
        int c = t;
        float bm = -1e30f; int bi = 0; int tc = 0;
        for (int q = 0; q < 256; ++q) {
            tc += scnt[c][q];
            float v = smax[c][q];
            if (v > bm) { bm = v; bi = sidx[c][q]; }
            else if (v == bm && sidx[c][q] < bi) { bi = sidx[c][q]; }
        }
        fres[c] = bi;
        fcnt[c] = tc;
    }
    __syncthreads();

    float lab0 = labels[b * 4 + 0];
    float lab1 = labels[b * 4 + 1];
    float lab2 = labels[b * 4 + 2];
    float lab[3] = {lab0, lab1, lab2};

#pragma unroll
    for (int m = 0; m < NP / 256; ++m) {
        int j = t + m * 256;
        unsigned bb = bits[m];
        unsigned ob = 0;
#pragma unroll
        for (int c = 0; c < 3; ++c) {
            if (lab[c] > 0.0f) {
                unsigned bit;
                if (fcnt[c] <= 1) bit = (j == fres[c]) ? 1u : 0u;   // fallback: argmax only
                else              bit = (bb >> c) & 1u;
                ob |= bit << c;
            }
        }
        g_seed[b * NP + j] = (unsigned char)ob;
    }
}

// ---------------- K_gemm: xr = x @ W^T + b, logit = softmax -> d_out ----------------
__global__ void __launch_bounds__(256) k_gemm(const float* __restrict__ x,
                                              const float* __restrict__ Wt,
                                              const float* __restrict__ bias,
                                              float* __restrict__ out) {
    __shared__ float4 sW4[4 * (NC / 4)];   // 4 x 512 floats
    float* sW = (float*)sW4;
    int tid = threadIdx.x;
    for (int k = tid; k < 4 * NC; k += 256) sW[k] = Wt[k];
    __syncthreads();

    int warp = tid >> 5, lane = tid & 31;
    int row  = blockIdx.x * 8 + warp;
    const float4* xr = (const float4*)(x + (size_t)row * NC);

    float a0 = 0.f, a1 = 0.f, a2 = 0.f, a3 = 0.f;
#pragma unroll
    for (int c4 = 0; c4 < NC / 128; ++c4) {
        int k4 = lane + c4 * 32;           // float4 index within the row (0..127)
        float4 v  = xr[k4];
        float4 w0 = sW4[0 * 128 + k4];
        float4 w1 = sW4[1 * 128 + k4];
        float4 w2 = sW4[2 * 128 + k4];
        float4 w3 = sW4[3 * 128 + k4];
        a0 += v.x * w0.x + v.y * w0.y + v.z * w0.z + v.w * w0.w;
        a1 += v.x * w1.x + v.y * w1.y + v.z * w1.z + v.w * w1.w;
        a2 += v.x * w2.x + v.y * w2.y + v.z * w2.z + v.w * w2.w;
        a3 += v.x * w3.x + v.y * w3.y + v.z * w3.z + v.w * w3.w;
    }
#pragma unroll
    for (int off = 16; off; off >>= 1) {
        a0 += __shfl_down_sync(0xffffffffu, a0, off);
        a1 += __shfl_down_sync(0xffffffffu, a1, off);
        a2 += __shfl_down_sync(0xffffffffu, a2, off);
        a3 += __shfl_down_sync(0xffffffffu, a3, off);
    }
    if (lane == 0) {
        a0 += bias[0]; a1 += bias[1]; a2 += bias[2]; a3 += bias[3];
        float m = fmaxf(fmaxf(a0, a1), fmaxf(a2, a3));
        float e0 = expf(a0 - m), e1 = expf(a1 - m), e2 = expf(a2 - m), e3 = expf(a3 - m);
        float inv = 1.0f / (e0 + e1 + e2 + e3);
        ((float4*)out)[row] = make_float4(e0 * inv, e1 * inv, e2 * inv, e3 * inv);
    }
}

// ---------------- K_iou: per (b, i-tile, j-chunk) best-seed IoU ----------------
__global__ void __launch_bounds__(ITI) k_iou(const float4* __restrict__ rois) {
    __shared__ float4        s_roi[JCH];
    __shared__ float         s_area[JCH];
    __shared__ unsigned char s_seed[JCH];

    int b     = blockIdx.z;
    int jbase = blockIdx.y * JCH;
    int i     = blockIdx.x * ITI + threadIdx.x;

    for (int j = threadIdx.x; j < JCH; j += ITI) {
        float4 r = rois[b * NP + jbase + j];
        s_roi[j]  = r;
        s_area[j] = (r.z - r.x) * (r.w - r.y);
        s_seed[j] = g_seed[b * NP + jbase + j];
    }
    __syncthreads();

    float4 ri = rois[b * NP + i];
    float  ai = (ri.z - ri.x) * (ri.w - ri.y);

    float b0 = -1.f, b1 = -1.f, b2 = -1.f;
    int   i0 = 0, i1 = 0, i2 = 0;

#pragma unroll 4
    for (int jl = 0; jl < JCH; ++jl) {
        unsigned sb = s_seed[jl];
        if (sb == 0) continue;             // warp-uniform skip: j has no active-class seed
        float4 rj = s_roi[jl];
        float ltx = fmaxf(ri.x, rj.x);
        float lty = fmaxf(ri.y, rj.y);
        float rbx = fminf(ri.z, rj.z);
        float rby = fminf(ri.w, rj.w);
        float ww = fmaxf(rbx - ltx, 0.f);
        float hh = fmaxf(rby - lty, 0.f);
        float inter = ww * hh;
        float iou = __fdividef(inter, (ai + s_area[jl]) - inter);
        if (sb & 1u) { if (iou > b0) { b0 = iou; i0 = jl; } }
        if (sb & 2u) { if (iou > b1) { b1 = iou; i1 = jl; } }
        if (sb & 4u) { if (iou > b2) { b2 = iou; i2 = jl; } }
    }

    unsigned long long* gb = &g_best[(b * 3) * NP + i];
    if (b0 >= 0.f)
        atomicMax(&gb[0],
            ((unsigned long long)__float_as_uint(b0) << 11) | (unsigned)(2047 - (jbase + i0)));
    if (b1 >= 0.f)
        atomicMax(&gb[NP],
            ((unsigned long long)__float_as_uint(b1) << 11) | (unsigned)(2047 - (jbase + i1)));
    if (b2 >= 0.f)
        atomicMax(&gb[2 * NP],
            ((unsigned long long)__float_as_uint(b2) << 11) | (unsigned)(2047 - (jbase + i2)));
}

// ---------------- K_resolve: class chain, w lookup, imbalance ----------------
__global__ void __launch_bounds__(256) k_resolve(const float* __restrict__ pre_score) {
    int row = blockIdx.x * 256 + threadIdx.x;
    int b = row >> 11;
    int i = row & (NP - 1);

    float I = -1.0f, w = 1.0f;
    int a = 3;
#pragma unroll
    for (int c = 0; c < 3; ++c) {
        unsigned long long k = g_best[(b * 3 + c) * NP + i];
        if (k) {
            float biou = __uint_as_float((unsigned)(k >> 11));
            if (biou >= 0.5f && biou > I) {
                I = biou;
                int j = 2047 - (int)(k & 2047ull);
                w = pre_score[((b << 11) + j) * 4 + c];
                a = c;
            }
        }
    }
    g_a[row] = (unsigned char)a;
    g_w[row] = w;

#pragma unroll
    for (int c = 0; c < 4; ++c) {
        int n = __popc(__ballot_sync(0xffffffffu, a == c));
        if ((threadIdx.x & 31) == 0 && n) atomicAdd(&g_imb[c], n);
    }
}

// ---------------- K_loss: focal-loss weighted sum ----------------
__global__ void __launch_bounds__(256) k_loss(const float4* __restrict__ logit,
                                              const float* __restrict__ labels) {
    int row = blockIdx.x * 256 + threadIdx.x;

    float4 lg = logit[row];
    int a = g_a[row];
    float w = g_w[row];
    float la = (a == 0) ? lg.x : (a == 1) ? lg.y : (a == 2) ? lg.z : lg.w;

    float p = fminf(fmaxf(la, 1e-7f), 1.0f - 1e-7f);
    float omp = 1.0f - p;
    float fl = -logf(p) * omp * omp;

    int b = row >> 11;
    float lab_a = (a == 3) ? 1.0f : labels[b * 4 + a];
    float wq = 10.0f * expf(la) * (1.0f - lab_a) + lab_a;
    float imba = (float)g_imb[a];
    float term = (w * fl) / (imba + 1e-7f) * wq;

#pragma unroll
    for (int off = 16; off; off >>= 1) term += __shfl_down_sync(0xffffffffu, term, off);

    __shared__ float sred[8];
    int lane = threadIdx.x & 31, wp = threadIdx.x >> 5;
    if (lane == 0) sred[wp] = term;
    __syncthreads();
    if (wp == 0) {
        float v = (lane < 8) ? sred[lane] : 0.0f;
#pragma unroll
        for (int off = 4; off; off >>= 1) v += __shfl_down_sync(0xffffffffu, v, off);
        if (lane == 0) atomicAdd(&g_loss, v);
    }
}

// ---------------- K_final: scale and store scalar loss ----------------
__global__ void k_final(float* __restrict__ out, int loss_idx) {
    out[loss_idx] = g_loss * (1.0f / (float)NB);
}

// ---------------- launch ----------------
extern "C" void kernel_launch(void* const* d_in, const int* in_sizes, int n_in,
                              void* d_out, int out_size) {
    const float* inputs    = (const float*)d_in[0];
    const float* pre_score = (const float*)d_in[1];
    const float* labels    = (const float*)d_in[2];
    const float* rois      = (const float*)d_in[3];
    const float* fcw       = (const float*)d_in[4];
    const float* fcb       = (const float*)d_in[5];
    float* out = (float*)d_out;

    k_seeds<<<NB, 256>>>((const float4*)pre_score, labels);
    k_gemm<<<BP / 8, 256>>>(inputs, fcw, fcb, out);
    k_iou<<<dim3(NP / ITI, NP / JCH, NB), ITI>>>((const float4*)rois);
    k_resolve<<<BP / 256, 256>>>(pre_score);
    k_loss<<<BP / 256, 256>>>((const float4*)out, labels);
    k_final<<<1, 1>>>(out, out_size - 1);
}